// round 3
// baseline (speedup 1.0000x reference)
#include <cuda_runtime.h>
#include <cuda_bf16.h>
#include <cstdint>
#include <cstddef>

using bf16 = __nv_bfloat16;
using bf162 = __nv_bfloat162;

constexpr int Bdim = 8, Ldim = 512, Hdim = 768, Odim = 12;
constexpr int Kdim = Hdim;
constexpr float NEGC = 1000000000000.0f;

// CTA tile 128x256, warp tile 64x64 (8 warps: 2 in M x 4 in N), BK=32, 4 stages
constexpr int BM = 128, BN = 256, BK = 32, PAD = 8, LDS = BK + PAD;  // 40
constexpr int S = 4;
constexpr int KT = Kdim / BK;                 // 24
constexpr int ASTAGE = BM * LDS * 2;          // 10240 B
constexpr int BSTAGE = BN * LDS * 2;          // 20480 B
constexpr unsigned SMEM_DYN = S * (ASTAGE + BSTAGE);  // 122880 B

// ---------------- scratch ----------------------------------------------------
__device__ __align__(16) bf16 g_in [Bdim * Ldim * Hdim];
__device__ __align__(16) bf16 g_w1t[Odim * Hdim * Hdim];
__device__ __align__(16) bf16 g_U  [(size_t)Bdim * Odim * Ldim * Hdim];
__device__ float g_lina[Bdim * Ldim * Odim];
__device__ float g_linb[Bdim * Ldim * Odim];

// ---------------- helpers -----------------------------------------------------
__device__ __forceinline__ uint32_t s2u(const void* p) {
    return (uint32_t)__cvta_generic_to_shared(p);
}
__device__ __forceinline__ void cp16(uint32_t s, const void* g) {
    asm volatile("cp.async.cg.shared.global [%0], [%1], 16;" :: "r"(s), "l"(g));
}
__device__ __forceinline__ void cp_commit() {
    asm volatile("cp.async.commit_group;");
}
template <int N>
__device__ __forceinline__ void cp_wait() {
    asm volatile("cp.async.wait_group %0;" :: "n"(N));
}
__device__ __forceinline__ void mma_op(float* c, const uint32_t* a, const uint32_t* bq) {
    asm volatile(
        "mma.sync.aligned.m16n8k16.row.col.f32.bf16.bf16.f32 "
        "{%0,%1,%2,%3},{%4,%5,%6,%7},{%8,%9},{%0,%1,%2,%3};"
        : "+f"(c[0]), "+f"(c[1]), "+f"(c[2]), "+f"(c[3])
        : "r"(a[0]), "r"(a[1]), "r"(a[2]), "r"(a[3]), "r"(bq[0]), "r"(bq[1]));
}

// one BK=32 slab, warp tile 64x64
__device__ __forceinline__ void mma_slab(float acc[4][8][4],
                                         const bf16* As, const bf16* Bs,
                                         int wm, int wn, int lane) {
    int r = lane & 7, sub = lane >> 3;
    #pragma unroll
    for (int kk = 0; kk < BK; kk += 16) {
        uint32_t a[4][4], bq[8][2];
        #pragma unroll
        for (int mt = 0; mt < 4; mt++) {
            uint32_t addr = s2u(As + (wm * 64 + mt * 16 + (sub & 1) * 8 + r) * LDS
                                   + kk + (sub >> 1) * 8);
            asm volatile("ldmatrix.sync.aligned.m8n8.x4.shared.b16 {%0,%1,%2,%3}, [%4];"
                         : "=r"(a[mt][0]), "=r"(a[mt][1]), "=r"(a[mt][2]), "=r"(a[mt][3])
                         : "r"(addr));
        }
        #pragma unroll
        for (int p = 0; p < 4; p++) {
            uint32_t addr = s2u(Bs + (wn * 64 + p * 16 + (sub >> 1) * 8 + r) * LDS
                                   + kk + (sub & 1) * 8);
            uint32_t v0, v1, v2, v3;
            asm volatile("ldmatrix.sync.aligned.m8n8.x4.shared.b16 {%0,%1,%2,%3}, [%4];"
                         : "=r"(v0), "=r"(v1), "=r"(v2), "=r"(v3) : "r"(addr));
            bq[2 * p][0] = v0;     bq[2 * p][1] = v1;
            bq[2 * p + 1][0] = v2; bq[2 * p + 1][1] = v3;
        }
        #pragma unroll
        for (int mt = 0; mt < 4; mt++)
            #pragma unroll
            for (int nt = 0; nt < 8; nt++)
                mma_op(acc[mt][nt], a[mt], bq[nt]);
    }
}

// 128x256x768 NT-GEMM mainloop; A,B row-major K-contiguous
__device__ __forceinline__ void gemm_mainloop(const bf16* __restrict__ Ablk,
                                              const bf16* __restrict__ Bblk,
                                              float acc[4][8][4], char* smem) {
    int t = threadIdx.x;
    int lane = t & 31, warp = t >> 5;
    int wm = warp >> 2, wn = warp & 3;

    bf16* Asm = reinterpret_cast<bf16*>(smem);
    bf16* Bsm = reinterpret_cast<bf16*>(smem + S * ASTAGE);
    uint32_t aBase = s2u(Asm), bBase = s2u(Bsm);

    // per-thread load geometry: A row t (t<128), B row t; 4x16B chunks per row
    uint32_t aS = aBase + (uint32_t)(t * LDS * 2);
    uint32_t bS = bBase + (uint32_t)(t * LDS * 2);
    const bf16* aG = Ablk + (size_t)t * Kdim;
    const bf16* bG = Bblk + (size_t)t * Kdim;

    auto load_stage = [&](int kt, int st) {
        int koff = kt * BK;
        if (t < BM) {
            uint32_t d = aS + st * ASTAGE;
            #pragma unroll
            for (int c = 0; c < 4; c++) cp16(d + c * 16, aG + koff + c * 8);
        }
        uint32_t d = bS + st * BSTAGE;
        #pragma unroll
        for (int c = 0; c < 4; c++) cp16(d + c * 16, bG + koff + c * 8);
        cp_commit();
    };

    #pragma unroll
    for (int s = 0; s < S - 1; s++) load_stage(s, s);

    #pragma unroll 1
    for (int kt = 0; kt < KT; kt++) {
        cp_wait<S - 2>();
        __syncthreads();
        if (kt + S - 1 < KT) load_stage(kt + S - 1, (kt + S - 1) & (S - 1));
        else cp_commit();                       // keep group count uniform
        int buf = kt & (S - 1);
        mma_slab(acc, Asm + buf * (ASTAGE / 2), Bsm + buf * (BSTAGE / 2), wm, wn, lane);
    }
}

// ---------------- prep kernels ------------------------------------------------
__global__ void convert_in_kernel(const float* __restrict__ in) {
    int i = (blockIdx.x * blockDim.x + threadIdx.x) * 4;
    float4 v = *reinterpret_cast<const float4*>(in + i);
    *reinterpret_cast<bf162*>(&g_in[i])     = __floats2bfloat162_rn(v.x, v.y);
    *reinterpret_cast<bf162*>(&g_in[i + 2]) = __floats2bfloat162_rn(v.z, v.w);
}

__global__ void transpose_w1_kernel(const float* __restrict__ w1) {
    __shared__ float tile[32][33];
    int n0 = blockIdx.x * 32, i0 = blockIdx.y * 32;
    int tx = threadIdx.x, ty = threadIdx.y;
    #pragma unroll
    for (int k = 0; k < 32; k += 8)
        tile[ty + k][tx] = w1[(size_t)(i0 + ty + k) * (Odim * Hdim) + n0 + tx];
    __syncthreads();
    #pragma unroll
    for (int k = 0; k < 32; k += 8)
        g_w1t[(size_t)(n0 + ty + k) * Hdim + i0 + tx] = __float2bfloat16(tile[tx][ty + k]);
}

__global__ void lin_kernel(const float* __restrict__ in, const float* __restrict__ w2) {
    int row = blockIdx.x;
    int o = threadIdx.x >> 5, lane = threadIdx.x & 31;
    const float* x = in + (size_t)row * Hdim;
    float sa = 0.f, sb = 0.f;
    for (int i = lane; i < Hdim; i += 32) {
        float v = x[i];
        sa += v * w2[i * Odim + o];
        sb += v * w2[(Hdim + i) * Odim + o];
    }
    #pragma unroll
    for (int off = 16; off; off >>= 1) {
        sa += __shfl_xor_sync(0xffffffffu, sa, off);
        sb += __shfl_xor_sync(0xffffffffu, sb, off);
    }
    if (lane == 0) { g_lina[row * Odim + o] = sa; g_linb[row * Odim + o] = sb; }
}

// ---------------- GEMM 1: U = in @ W1t^T (M=4096, N=9216, K=768) -------------
__global__ __launch_bounds__(256, 1) void gemm1_kernel() {
    extern __shared__ char smem[];
    const bf16* Ablk = g_in  + (size_t)blockIdx.y * BM * Kdim;
    const bf16* Bblk = g_w1t + (size_t)blockIdx.x * BN * Kdim;
    float acc[4][8][4];
    #pragma unroll
    for (int i = 0; i < 4; i++)
        #pragma unroll
        for (int j = 0; j < 8; j++)
            #pragma unroll
            for (int e = 0; e < 4; e++) acc[i][j][e] = 0.f;
    gemm_mainloop(Ablk, Bblk, acc, smem);

    int t = threadIdx.x, lane = t & 31, warp = t >> 5;
    int wm = warp >> 2, wn = warp & 3;
    int g = lane >> 2, tig = lane & 3;
    int o  = (blockIdx.x * BN) / Hdim;            // 256 | 768, no straddle
    int jb = blockIdx.x * BN - o * Hdim;
    #pragma unroll
    for (int mt = 0; mt < 4; mt++) {
        #pragma unroll
        for (int h = 0; h < 2; h++) {
            int R = blockIdx.y * BM + wm * 64 + mt * 16 + g + h * 8;
            int b = R >> 9, x = R & (Ldim - 1);
            size_t base = ((size_t)(b * Odim + o) * Ldim + x) * Hdim + jb + wn * 64;
            #pragma unroll
            for (int nt = 0; nt < 8; nt++) {
                *reinterpret_cast<bf162*>(&g_U[base + nt * 8 + 2 * tig]) =
                    __floats2bfloat162_rn(acc[mt][nt][h * 2], acc[mt][nt][h * 2 + 1]);
            }
        }
    }
}

// ------- GEMM 2 + fused epilogue ---------------------------------------------
__global__ __launch_bounds__(256, 1) void gemm2_kernel(const float* __restrict__ w2,
                                                       const int* __restrict__ mask,
                                                       float* __restrict__ out) {
    extern __shared__ char smem[];
    __shared__ int   rowm[BM];
    __shared__ float rowv[BM];
    __shared__ int   colm[BN];
    __shared__ float colv[BN];

    int z = blockIdx.z;
    int b = z / Odim, o = z - b * Odim;
    const bf16* Ablk = g_U  + ((size_t)z * Ldim + blockIdx.y * BM) * Kdim;
    const bf16* Bblk = g_in + ((size_t)b * Ldim + blockIdx.x * BN) * Kdim;
    float acc[4][8][4];
    #pragma unroll
    for (int i = 0; i < 4; i++)
        #pragma unroll
        for (int j = 0; j < 8; j++)
            #pragma unroll
            for (int e = 0; e < 4; e++) acc[i][j][e] = 0.f;
    gemm_mainloop(Ablk, Bblk, acc, smem);

    int t = threadIdx.x, lane = t & 31, warp = t >> 5;
    int wm = warp >> 2, wn = warp & 3;
    int g = lane >> 2, tig = lane & 3;
    float bias = w2[2 * Hdim * Odim + o];
    if (t < BM) {
        int x = blockIdx.y * BM + t;
        rowm[t] = mask[b * Ldim + x];
        rowv[t] = g_lina[(b * Ldim + x) * Odim + o] + bias;
    }
    {
        int y = blockIdx.x * BN + t;
        colm[t] = mask[b * Ldim + y];
        colv[t] = g_linb[(b * Ldim + y) * Odim + o];
    }
    __syncthreads();

    int x0l = wm * 64;                  // local row base within CTA
    int y0l = wn * 64;
    #pragma unroll
    for (int mt = 0; mt < 4; mt++) {
        #pragma unroll
        for (int h = 0; h < 2; h++) {
            int rl = x0l + mt * 16 + g + h * 8;
            int x = blockIdx.y * BM + rl;
            int rm = rowm[rl];
            float rv = rowv[rl];
            float* orow = out + ((size_t)z * Ldim + x) * Ldim + blockIdx.x * BN;
            #pragma unroll
            for (int nt = 0; nt < 8; nt++) {
                int cl = y0l + nt * 8 + 2 * tig;
                int y = blockIdx.x * BN + cl;
                float2 v;
                v.x = (rm && colm[cl])     ? (acc[mt][nt][h * 2]     + rv + colv[cl])     : -NEGC;
                v.y = (rm && colm[cl + 1]) ? (acc[mt][nt][h * 2 + 1] + rv + colv[cl + 1]) : -NEGC;
                if (y     < x) v.x -= NEGC;
                if (y + 1 < x) v.y -= NEGC;
                *reinterpret_cast<float2*>(orow + cl) = v;
            }
        }
    }
}

// ---------------- launch ------------------------------------------------------
extern "C" void kernel_launch(void* const* d_in, const int* in_sizes, int n_in,
                              void* d_out, int out_size) {
    (void)out_size;
    const float* inputs = nullptr; const float* w1 = nullptr;
    const float* w2 = nullptr;     const int* mask = nullptr;
    for (int i = 0; i < n_in; i++) {
        int s = in_sizes[i];
        if      (s == Bdim * Ldim * Hdim)    inputs = (const float*)d_in[i];
        else if (s == Hdim * Odim * Hdim)    w1     = (const float*)d_in[i];
        else if (s == (2 * Hdim + 1) * Odim) w2     = (const float*)d_in[i];
        else if (s == Bdim * Ldim)           mask   = (const int*)d_in[i];
    }
    float* out = (float*)d_out;

    cudaFuncSetAttribute(gemm1_kernel, cudaFuncAttributeMaxDynamicSharedMemorySize, SMEM_DYN);
    cudaFuncSetAttribute(gemm2_kernel, cudaFuncAttributeMaxDynamicSharedMemorySize, SMEM_DYN);

    convert_in_kernel<<<(Bdim * Ldim * Hdim) / 1024, 256>>>(inputs);
    transpose_w1_kernel<<<dim3((Odim * Hdim) / 32, Hdim / 32), dim3(32, 8)>>>(w1);
    lin_kernel<<<Bdim * Ldim, 384>>>(inputs, w2);
    gemm1_kernel<<<dim3((Odim * Hdim) / BN, (Bdim * Ldim) / BM), 256, SMEM_DYN>>>();
    gemm2_kernel<<<dim3(Ldim / BN, Ldim / BM, Bdim * Odim), 256, SMEM_DYN>>>(w2, mask, out);
}

// round 4
// speedup vs baseline: 1.2835x; 1.2835x over previous
#include <cuda_runtime.h>
#include <cuda_bf16.h>
#include <cstdint>
#include <cstddef>

using bf16 = __nv_bfloat16;
using bf162 = __nv_bfloat162;

constexpr int Bdim = 8, Ldim = 512, Hdim = 768, Odim = 12;
constexpr int Kdim = Hdim;
constexpr float NEGC = 1000000000000.0f;

// CTA tile 128x128, warp tile 64x32 (8 warps: 2M x 4N), BK=32, 4 stages
constexpr int BM = 128, BN = 128, BK = 32, PAD = 8, LDS = BK + PAD;  // 40
constexpr int S = 4;
constexpr int KT = Kdim / BK;               // 24
constexpr int STAGE = BM * LDS * 2;         // 10240 B per operand per stage
constexpr unsigned SMEM_DYN = 2u * S * STAGE;  // 81920 B

// ---------------- scratch ----------------------------------------------------
__device__ __align__(16) bf16 g_in [Bdim * Ldim * Hdim];
__device__ __align__(16) bf16 g_w1t[Odim * Hdim * Hdim];
__device__ __align__(16) bf16 g_U  [(size_t)Bdim * Odim * Ldim * Hdim];
__device__ float g_lina[Bdim * Ldim * Odim];
__device__ float g_linb[Bdim * Ldim * Odim];

// ---------------- helpers -----------------------------------------------------
__device__ __forceinline__ uint32_t s2u(const void* p) {
    return (uint32_t)__cvta_generic_to_shared(p);
}
__device__ __forceinline__ void cp16(uint32_t s, const void* g) {
    asm volatile("cp.async.cg.shared.global [%0], [%1], 16;" :: "r"(s), "l"(g));
}
__device__ __forceinline__ void cp_commit() {
    asm volatile("cp.async.commit_group;");
}
template <int N>
__device__ __forceinline__ void cp_wait() {
    asm volatile("cp.async.wait_group %0;" :: "n"(N));
}
__device__ __forceinline__ void mma_op(float* c, const uint32_t* a, const uint32_t* bq) {
    asm volatile(
        "mma.sync.aligned.m16n8k16.row.col.f32.bf16.bf16.f32 "
        "{%0,%1,%2,%3},{%4,%5,%6,%7},{%8,%9},{%0,%1,%2,%3};"
        : "+f"(c[0]), "+f"(c[1]), "+f"(c[2]), "+f"(c[3])
        : "r"(a[0]), "r"(a[1]), "r"(a[2]), "r"(a[3]), "r"(bq[0]), "r"(bq[1]));
}

// one BK=32 slab, warp tile 64x32 (proven Round-1 fragment mapping)
__device__ __forceinline__ void mma_slab(float acc[4][4][4],
                                         const bf16* As, const bf16* Bs,
                                         int wm, int wn, int lane) {
    int r = lane & 7, sub = lane >> 3;
    #pragma unroll
    for (int kk = 0; kk < BK; kk += 16) {
        uint32_t a[4][4], bq[4][2];
        #pragma unroll
        for (int mt = 0; mt < 4; mt++) {
            uint32_t addr = s2u(As + (wm * 64 + mt * 16 + (sub & 1) * 8 + r) * LDS
                                   + kk + (sub >> 1) * 8);
            asm volatile("ldmatrix.sync.aligned.m8n8.x4.shared.b16 {%0,%1,%2,%3}, [%4];"
                         : "=r"(a[mt][0]), "=r"(a[mt][1]), "=r"(a[mt][2]), "=r"(a[mt][3])
                         : "r"(addr));
        }
        #pragma unroll
        for (int p = 0; p < 2; p++) {
            uint32_t addr = s2u(Bs + (wn * 32 + p * 16 + (sub >> 1) * 8 + r) * LDS
                                   + kk + (sub & 1) * 8);
            uint32_t v0, v1, v2, v3;
            asm volatile("ldmatrix.sync.aligned.m8n8.x4.shared.b16 {%0,%1,%2,%3}, [%4];"
                         : "=r"(v0), "=r"(v1), "=r"(v2), "=r"(v3) : "r"(addr));
            bq[2 * p][0] = v0;     bq[2 * p][1] = v1;
            bq[2 * p + 1][0] = v2; bq[2 * p + 1][1] = v3;
        }
        #pragma unroll
        for (int mt = 0; mt < 4; mt++)
            #pragma unroll
            for (int nt = 0; nt < 4; nt++)
                mma_op(acc[mt][nt], a[mt], bq[nt]);
    }
}

// 128x128x768 NT-GEMM mainloop; A,B row-major K-contiguous; 4-stage, 1 sync/slab
__device__ __forceinline__ void gemm_mainloop(const bf16* __restrict__ Ablk,
                                              const bf16* __restrict__ Bblk,
                                              float acc[4][4][4], char* smem) {
    int t = threadIdx.x;
    int lane = t & 31, warp = t >> 5;
    int wm = warp >> 2, wn = warp & 3;

    bf16* Asm = reinterpret_cast<bf16*>(smem);
    bf16* Bsm = reinterpret_cast<bf16*>(smem + S * STAGE);
    uint32_t aBase = s2u(Asm), bBase = s2u(Bsm);

    // thread t: row = t>>1, byte-col = (t&1)*32; 2x16B chunks per operand
    int row = t >> 1, cb = (t & 1) * 32;
    uint32_t aS = aBase + (uint32_t)(row * (LDS * 2) + cb);
    uint32_t bS = bBase + (uint32_t)(row * (LDS * 2) + cb);
    const char* aG = reinterpret_cast<const char*>(Ablk) + (size_t)row * Kdim * 2 + cb;
    const char* bG = reinterpret_cast<const char*>(Bblk) + (size_t)row * Kdim * 2 + cb;

    auto load_stage = [&](int kt, int st) {
        int koff = kt * (BK * 2);
        uint32_t da = aS + st * STAGE;
        uint32_t db = bS + st * STAGE;
        cp16(da, aG + koff);       cp16(da + 16, aG + koff + 16);
        cp16(db, bG + koff);       cp16(db + 16, bG + koff + 16);
        cp_commit();
    };

    #pragma unroll
    for (int s = 0; s < S - 1; s++) load_stage(s, s);

    #pragma unroll 1
    for (int kt = 0; kt < KT; kt++) {
        cp_wait<S - 2>();
        __syncthreads();
        if (kt + S - 1 < KT) load_stage(kt + S - 1, (kt + S - 1) & (S - 1));
        else cp_commit();                     // keep group accounting uniform
        int buf = kt & (S - 1);
        mma_slab(acc, Asm + buf * (STAGE / 2), Bsm + buf * (STAGE / 2), wm, wn, lane);
    }
}

// ---------------- prep kernels ------------------------------------------------
__global__ void convert_in_kernel(const float* __restrict__ in) {
    int i = (blockIdx.x * blockDim.x + threadIdx.x) * 4;
    float4 v = *reinterpret_cast<const float4*>(in + i);
    *reinterpret_cast<bf162*>(&g_in[i])     = __floats2bfloat162_rn(v.x, v.y);
    *reinterpret_cast<bf162*>(&g_in[i + 2]) = __floats2bfloat162_rn(v.z, v.w);
}

__global__ void transpose_w1_kernel(const float* __restrict__ w1) {
    __shared__ float tile[32][33];
    int n0 = blockIdx.x * 32, i0 = blockIdx.y * 32;
    int tx = threadIdx.x, ty = threadIdx.y;
    #pragma unroll
    for (int k = 0; k < 32; k += 8)
        tile[ty + k][tx] = w1[(size_t)(i0 + ty + k) * (Odim * Hdim) + n0 + tx];
    __syncthreads();
    #pragma unroll
    for (int k = 0; k < 32; k += 8)
        g_w1t[(size_t)(n0 + ty + k) * Hdim + i0 + tx] = __float2bfloat16(tile[tx][ty + k]);
}

__global__ void lin_kernel(const float* __restrict__ in, const float* __restrict__ w2) {
    int row = blockIdx.x;
    int o = threadIdx.x >> 5, lane = threadIdx.x & 31;
    const float* x = in + (size_t)row * Hdim;
    float sa = 0.f, sb = 0.f;
    for (int i = lane; i < Hdim; i += 32) {
        float v = x[i];
        sa += v * w2[i * Odim + o];
        sb += v * w2[(Hdim + i) * Odim + o];
    }
    #pragma unroll
    for (int off = 16; off; off >>= 1) {
        sa += __shfl_xor_sync(0xffffffffu, sa, off);
        sb += __shfl_xor_sync(0xffffffffu, sb, off);
    }
    if (lane == 0) { g_lina[row * Odim + o] = sa; g_linb[row * Odim + o] = sb; }
}

// ---------------- GEMM 1: U = in @ W1t^T (M=4096, N=9216, K=768) -------------
__global__ __launch_bounds__(256, 2) void gemm1_kernel() {
    extern __shared__ char smem[];
    const bf16* Ablk = g_in  + (size_t)blockIdx.y * BM * Kdim;
    const bf16* Bblk = g_w1t + (size_t)blockIdx.x * BN * Kdim;
    float acc[4][4][4];
    #pragma unroll
    for (int i = 0; i < 4; i++)
        #pragma unroll
        for (int j = 0; j < 4; j++)
            #pragma unroll
            for (int e = 0; e < 4; e++) acc[i][j][e] = 0.f;
    gemm_mainloop(Ablk, Bblk, acc, smem);

    int t = threadIdx.x, lane = t & 31, warp = t >> 5;
    int wm = warp >> 2, wn = warp & 3;
    int g = lane >> 2, tig = lane & 3;
    int o  = (blockIdx.x * BN) / Hdim;
    int jb = blockIdx.x * BN - o * Hdim;
    #pragma unroll
    for (int mt = 0; mt < 4; mt++) {
        int R = blockIdx.y * BM + wm * 64 + mt * 16 + g;
        int b = R >> 9, x = R & (Ldim - 1);
        #pragma unroll
        for (int nt = 0; nt < 4; nt++) {
            int j = jb + wn * 32 + nt * 8 + 2 * tig;
            size_t base = ((size_t)(b * Odim + o) * Ldim + x) * Hdim + j;
            *reinterpret_cast<bf162*>(&g_U[base]) =
                __floats2bfloat162_rn(acc[mt][nt][0], acc[mt][nt][1]);
            *reinterpret_cast<bf162*>(&g_U[base + (size_t)8 * Hdim]) =
                __floats2bfloat162_rn(acc[mt][nt][2], acc[mt][nt][3]);
        }
    }
}

// ------- GEMM 2 + fused epilogue ---------------------------------------------
__global__ __launch_bounds__(256, 2) void gemm2_kernel(const float* __restrict__ w2,
                                                       const int* __restrict__ mask,
                                                       float* __restrict__ out) {
    extern __shared__ char smem[];
    __shared__ int   rowm[BM];
    __shared__ float rowv[BM];
    __shared__ int   colm[BN];
    __shared__ float colv[BN];

    int z = blockIdx.z;
    int b = z / Odim, o = z - b * Odim;
    const bf16* Ablk = g_U  + ((size_t)z * Ldim + blockIdx.y * BM) * Kdim;
    const bf16* Bblk = g_in + ((size_t)b * Ldim + blockIdx.x * BN) * Kdim;
    float acc[4][4][4];
    #pragma unroll
    for (int i = 0; i < 4; i++)
        #pragma unroll
        for (int j = 0; j < 4; j++)
            #pragma unroll
            for (int e = 0; e < 4; e++) acc[i][j][e] = 0.f;
    gemm_mainloop(Ablk, Bblk, acc, smem);

    int t = threadIdx.x, lane = t & 31, warp = t >> 5;
    int wm = warp >> 2, wn = warp & 3;
    int g = lane >> 2, tig = lane & 3;
    float bias = w2[2 * Hdim * Odim + o];
    if (t < BM) {
        int x = blockIdx.y * BM + t;
        rowm[t] = mask[b * Ldim + x];
        rowv[t] = g_lina[(b * Ldim + x) * Odim + o] + bias;
        int y = blockIdx.x * BN + t;
        colm[t] = mask[b * Ldim + y];
        colv[t] = g_linb[(b * Ldim + y) * Odim + o];
    }
    __syncthreads();

    #pragma unroll
    for (int mt = 0; mt < 4; mt++) {
        #pragma unroll
        for (int h = 0; h < 2; h++) {
            int rl = wm * 64 + mt * 16 + g + h * 8;
            int x = blockIdx.y * BM + rl;
            int rm = rowm[rl];
            float rv = rowv[rl];
            float* orow = out + ((size_t)z * Ldim + x) * Ldim + blockIdx.x * BN;
            #pragma unroll
            for (int nt = 0; nt < 4; nt++) {
                int cl = wn * 32 + nt * 8 + 2 * tig;
                int y = blockIdx.x * BN + cl;
                float2 v;
                v.x = (rm && colm[cl])     ? (acc[mt][nt][h * 2]     + rv + colv[cl])     : -NEGC;
                v.y = (rm && colm[cl + 1]) ? (acc[mt][nt][h * 2 + 1] + rv + colv[cl + 1]) : -NEGC;
                if (y     < x) v.x -= NEGC;
                if (y + 1 < x) v.y -= NEGC;
                *reinterpret_cast<float2*>(orow + cl) = v;
            }
        }
    }
}

// ---------------- launch ------------------------------------------------------
extern "C" void kernel_launch(void* const* d_in, const int* in_sizes, int n_in,
                              void* d_out, int out_size) {
    (void)out_size;
    const float* inputs = nullptr; const float* w1 = nullptr;
    const float* w2 = nullptr;     const int* mask = nullptr;
    for (int i = 0; i < n_in; i++) {
        int s = in_sizes[i];
        if      (s == Bdim * Ldim * Hdim)    inputs = (const float*)d_in[i];
        else if (s == Hdim * Odim * Hdim)    w1     = (const float*)d_in[i];
        else if (s == (2 * Hdim + 1) * Odim) w2     = (const float*)d_in[i];
        else if (s == Bdim * Ldim)           mask   = (const int*)d_in[i];
    }
    float* out = (float*)d_out;

    cudaFuncSetAttribute(gemm1_kernel, cudaFuncAttributeMaxDynamicSharedMemorySize, SMEM_DYN);
    cudaFuncSetAttribute(gemm2_kernel, cudaFuncAttributeMaxDynamicSharedMemorySize, SMEM_DYN);

    convert_in_kernel<<<(Bdim * Ldim * Hdim) / 1024, 256>>>(inputs);
    transpose_w1_kernel<<<dim3((Odim * Hdim) / 32, Hdim / 32), dim3(32, 8)>>>(w1);
    lin_kernel<<<Bdim * Ldim, 384>>>(inputs, w2);
    gemm1_kernel<<<dim3((Odim * Hdim) / BN, (Bdim * Ldim) / BM), 256, SMEM_DYN>>>();
    gemm2_kernel<<<dim3(Ldim / BN, Ldim / BM, Bdim * Odim), 256, SMEM_DYN>>>(w2, mask, out);
}

// round 5
// speedup vs baseline: 1.4019x; 1.0923x over previous
#include <cuda_runtime.h>
#include <cuda_bf16.h>
#include <cstdint>
#include <cstddef>

constexpr int Bdim = 8, Ldim = 512, Hdim = 768, Odim = 12;
constexpr int Kdim = Hdim;                    // bytes per row in fp8 (= elements)
constexpr float NEGC = 1000000000000.0f;

// CTA tile 128x128, warp tile 64x32 (8 warps: 2M x 4N), K-slab 64 fp8 (=64B), 4 stages
constexpr int BM = 128, BN = 128, BKB = 64, PADB = 16, LDSB = BKB + PADB;  // 80 B
constexpr int S = 4;
constexpr int KT = Kdim / BKB;                // 12
constexpr int STAGE = BM * LDSB;              // 10240 B per operand per stage
constexpr unsigned SMEM_DYN = 2u * S * STAGE; // 81920 B

// ---------------- scratch (fp8 e4m3 storage) ---------------------------------
__device__ __align__(16) uint8_t g_in [Bdim * Ldim * Hdim];                 // fp8(x)
__device__ __align__(16) uint8_t g_w1t[Odim * Hdim * Hdim];                 // fp8(16*W1^T)
__device__ __align__(16) uint8_t g_U  [(size_t)Bdim * Odim * Ldim * Hdim]; // fp8(U)
__device__ float g_lina[Bdim * Ldim * Odim];
__device__ float g_linb[Bdim * Ldim * Odim];

// ---------------- helpers -----------------------------------------------------
__device__ __forceinline__ uint32_t s2u(const void* p) {
    return (uint32_t)__cvta_generic_to_shared(p);
}
__device__ __forceinline__ void cp16(uint32_t s, const void* g) {
    asm volatile("cp.async.cg.shared.global [%0], [%1], 16;" :: "r"(s), "l"(g));
}
__device__ __forceinline__ void cp_commit() {
    asm volatile("cp.async.commit_group;");
}
template <int N>
__device__ __forceinline__ void cp_wait() {
    asm volatile("cp.async.wait_group %0;" :: "n"(N));
}
// packs lo into byte0, hi into byte1
__device__ __forceinline__ uint16_t pack_e4m3x2(float lo, float hi) {
    uint16_t v;
    asm volatile("cvt.rn.satfinite.e4m3x2.f32 %0, %1, %2;" : "=h"(v) : "f"(hi), "f"(lo));
    return v;
}
__device__ __forceinline__ void mma_op(float* c, const uint32_t* a, const uint32_t* bq) {
    asm volatile(
        "mma.sync.aligned.m16n8k32.row.col.f32.e4m3.e4m3.f32 "
        "{%0,%1,%2,%3},{%4,%5,%6,%7},{%8,%9},{%0,%1,%2,%3};"
        : "+f"(c[0]), "+f"(c[1]), "+f"(c[2]), "+f"(c[3])
        : "r"(a[0]), "r"(a[1]), "r"(a[2]), "r"(a[3]), "r"(bq[0]), "r"(bq[1]));
}

// one 64B K-slab (2 k-steps of 32 fp8), warp tile 64x32
__device__ __forceinline__ void mma_slab(float acc[4][4][4],
                                         const uint8_t* As, const uint8_t* Bs,
                                         int wm, int wn, int lane) {
    int r = lane & 7, sub = lane >> 3;
    #pragma unroll
    for (int kk = 0; kk < BKB; kk += 32) {    // 32 bytes = k32 per mma
        uint32_t a[4][4], bq[4][2];
        #pragma unroll
        for (int mt = 0; mt < 4; mt++) {
            uint32_t addr = s2u(As + (wm * 64 + mt * 16 + (sub & 1) * 8 + r) * LDSB
                                   + kk + (sub >> 1) * 16);
            asm volatile("ldmatrix.sync.aligned.m8n8.x4.shared.b16 {%0,%1,%2,%3}, [%4];"
                         : "=r"(a[mt][0]), "=r"(a[mt][1]), "=r"(a[mt][2]), "=r"(a[mt][3])
                         : "r"(addr));
        }
        #pragma unroll
        for (int p = 0; p < 2; p++) {
            uint32_t addr = s2u(Bs + (wn * 32 + p * 16 + (sub >> 1) * 8 + r) * LDSB
                                   + kk + (sub & 1) * 16);
            uint32_t v0, v1, v2, v3;
            asm volatile("ldmatrix.sync.aligned.m8n8.x4.shared.b16 {%0,%1,%2,%3}, [%4];"
                         : "=r"(v0), "=r"(v1), "=r"(v2), "=r"(v3) : "r"(addr));
            bq[2 * p][0] = v0;     bq[2 * p][1] = v1;
            bq[2 * p + 1][0] = v2; bq[2 * p + 1][1] = v3;
        }
        #pragma unroll
        for (int mt = 0; mt < 4; mt++)
            #pragma unroll
            for (int nt = 0; nt < 4; nt++)
                mma_op(acc[mt][nt], a[mt], bq[nt]);
    }
}

// 128x128x768 NT-GEMM mainloop over fp8 operands (row-major, K-contiguous)
__device__ __forceinline__ void gemm_mainloop(const uint8_t* __restrict__ Ablk,
                                              const uint8_t* __restrict__ Bblk,
                                              float acc[4][4][4], char* smem) {
    int t = threadIdx.x;
    int lane = t & 31, warp = t >> 5;
    int wm = warp >> 2, wn = warp & 3;

    uint8_t* Asm = reinterpret_cast<uint8_t*>(smem);
    uint8_t* Bsm = reinterpret_cast<uint8_t*>(smem + S * STAGE);
    uint32_t aBase = s2u(Asm), bBase = s2u(Bsm);

    int row = t >> 1, cb = (t & 1) * 32;      // each thread: 32B of one 64B row
    uint32_t aS = aBase + (uint32_t)(row * LDSB + cb);
    uint32_t bS = bBase + (uint32_t)(row * LDSB + cb);
    const uint8_t* aG = Ablk + (size_t)row * Kdim + cb;
    const uint8_t* bG = Bblk + (size_t)row * Kdim + cb;

    auto load_stage = [&](int kt, int st) {
        int koff = kt * BKB;
        uint32_t da = aS + st * STAGE;
        uint32_t db = bS + st * STAGE;
        cp16(da, aG + koff);  cp16(da + 16, aG + koff + 16);
        cp16(db, bG + koff);  cp16(db + 16, bG + koff + 16);
        cp_commit();
    };

    #pragma unroll
    for (int s = 0; s < S - 1; s++) load_stage(s, s);

    #pragma unroll 1
    for (int kt = 0; kt < KT; kt++) {
        cp_wait<S - 2>();
        __syncthreads();
        if (kt + S - 1 < KT) load_stage(kt + S - 1, (kt + S - 1) & (S - 1));
        else cp_commit();
        int buf = kt & (S - 1);
        mma_slab(acc, Asm + buf * STAGE, Bsm + buf * STAGE, wm, wn, lane);
    }
}

// ---------------- prep kernels ------------------------------------------------
__global__ void convert_in_kernel(const float* __restrict__ in) {
    int i = (blockIdx.x * blockDim.x + threadIdx.x) * 4;
    float4 v = *reinterpret_cast<const float4*>(in + i);
    uint32_t p = (uint32_t)pack_e4m3x2(v.x, v.y)
               | ((uint32_t)pack_e4m3x2(v.z, v.w) << 16);
    *reinterpret_cast<uint32_t*>(&g_in[i]) = p;
}

__global__ void transpose_w1_kernel(const float* __restrict__ w1) {
    __shared__ float tile[32][33];
    int n0 = blockIdx.x * 32, i0 = blockIdx.y * 32;
    int tx = threadIdx.x, ty = threadIdx.y;
    #pragma unroll
    for (int k = 0; k < 32; k += 8)
        tile[ty + k][tx] = w1[(size_t)(i0 + ty + k) * (Odim * Hdim) + n0 + tx];
    __syncthreads();
    #pragma unroll
    for (int k = 0; k < 32; k += 8) {
        uint16_t q = pack_e4m3x2(tile[tx][ty + k] * 16.0f, 0.0f);
        g_w1t[(size_t)(n0 + ty + k) * Hdim + i0 + tx] = (uint8_t)(q & 0xFF);
    }
}

__global__ void lin_kernel(const float* __restrict__ in, const float* __restrict__ w2) {
    int row = blockIdx.x;
    int o = threadIdx.x >> 5, lane = threadIdx.x & 31;
    const float* x = in + (size_t)row * Hdim;
    float sa = 0.f, sb = 0.f;
    for (int i = lane; i < Hdim; i += 32) {
        float v = x[i];
        sa += v * w2[i * Odim + o];
        sb += v * w2[(Hdim + i) * Odim + o];
    }
    #pragma unroll
    for (int off = 16; off; off >>= 1) {
        sa += __shfl_xor_sync(0xffffffffu, sa, off);
        sb += __shfl_xor_sync(0xffffffffu, sb, off);
    }
    if (lane == 0) { g_lina[row * Odim + o] = sa; g_linb[row * Odim + o] = sb; }
}

// ---------------- GEMM 1: 16U = fp8(x) @ fp8(16*W1)^T ------------------------
__global__ __launch_bounds__(256, 2) void gemm1_kernel() {
    extern __shared__ char smem[];
    const uint8_t* Ablk = g_in  + (size_t)blockIdx.y * BM * Kdim;
    const uint8_t* Bblk = g_w1t + (size_t)blockIdx.x * BN * Kdim;
    float acc[4][4][4];
    #pragma unroll
    for (int i = 0; i < 4; i++)
        #pragma unroll
        for (int j = 0; j < 4; j++)
            #pragma unroll
            for (int e = 0; e < 4; e++) acc[i][j][e] = 0.f;
    gemm_mainloop(Ablk, Bblk, acc, smem);

    int t = threadIdx.x, lane = t & 31, warp = t >> 5;
    int wm = warp >> 2, wn = warp & 3;
    int g = lane >> 2, tig = lane & 3;
    int o  = (blockIdx.x * BN) / Hdim;        // 128 | 768: no straddle
    int jb = blockIdx.x * BN - o * Hdim;
    constexpr float sc = 1.0f / 16.0f;        // undo W1*16 scaling
    #pragma unroll
    for (int mt = 0; mt < 4; mt++) {
        int R = blockIdx.y * BM + wm * 64 + mt * 16 + g;
        int b = R >> 9, x = R & (Ldim - 1);
        #pragma unroll
        for (int nt = 0; nt < 4; nt++) {
            int j = jb + wn * 32 + nt * 8 + 2 * tig;
            size_t base = ((size_t)(b * Odim + o) * Ldim + x) * Hdim + j;
            *reinterpret_cast<uint16_t*>(&g_U[base]) =
                pack_e4m3x2(acc[mt][nt][0] * sc, acc[mt][nt][1] * sc);
            *reinterpret_cast<uint16_t*>(&g_U[base + (size_t)8 * Hdim]) =
                pack_e4m3x2(acc[mt][nt][2] * sc, acc[mt][nt][3] * sc);
        }
    }
}

// ------- GEMM 2 + fused epilogue ---------------------------------------------
__global__ __launch_bounds__(256, 2) void gemm2_kernel(const float* __restrict__ w2,
                                                       const int* __restrict__ mask,
                                                       float* __restrict__ out) {
    extern __shared__ char smem[];
    __shared__ int   rowm[BM];
    __shared__ float rowv[BM];
    __shared__ int   colm[BN];
    __shared__ float colv[BN];

    int z = blockIdx.z;
    int b = z / Odim, o = z - b * Odim;
    const uint8_t* Ablk = g_U  + ((size_t)z * Ldim + blockIdx.y * BM) * Kdim;
    const uint8_t* Bblk = g_in + ((size_t)b * Ldim + blockIdx.x * BN) * Kdim;
    float acc[4][4][4];
    #pragma unroll
    for (int i = 0; i < 4; i++)
        #pragma unroll
        for (int j = 0; j < 4; j++)
            #pragma unroll
            for (int e = 0; e < 4; e++) acc[i][j][e] = 0.f;
    gemm_mainloop(Ablk, Bblk, acc, smem);

    int t = threadIdx.x, lane = t & 31, warp = t >> 5;
    int wm = warp >> 2, wn = warp & 3;
    int g = lane >> 2, tig = lane & 3;
    float bias = w2[2 * Hdim * Odim + o];
    if (t < BM) {
        int x = blockIdx.y * BM + t;
        rowm[t] = mask[b * Ldim + x];
        rowv[t] = g_lina[(b * Ldim + x) * Odim + o] + bias;
        int y = blockIdx.x * BN + t;
        colm[t] = mask[b * Ldim + y];
        colv[t] = g_linb[(b * Ldim + y) * Odim + o];
    }
    __syncthreads();

    #pragma unroll
    for (int mt = 0; mt < 4; mt++) {
        #pragma unroll
        for (int h = 0; h < 2; h++) {
            int rl = wm * 64 + mt * 16 + g + h * 8;
            int x = blockIdx.y * BM + rl;
            int rm = rowm[rl];
            float rv = rowv[rl];
            float* orow = out + ((size_t)z * Ldim + x) * Ldim + blockIdx.x * BN;
            #pragma unroll
            for (int nt = 0; nt < 4; nt++) {
                int cl = wn * 32 + nt * 8 + 2 * tig;
                int y = blockIdx.x * BN + cl;
                float2 v;
                v.x = (rm && colm[cl])     ? (acc[mt][nt][h * 2]     + rv + colv[cl])     : -NEGC;
                v.y = (rm && colm[cl + 1]) ? (acc[mt][nt][h * 2 + 1] + rv + colv[cl + 1]) : -NEGC;
                if (y     < x) v.x -= NEGC;
                if (y + 1 < x) v.y -= NEGC;
                *reinterpret_cast<float2*>(orow + cl) = v;
            }
        }
    }
}

// ---------------- launch ------------------------------------------------------
extern "C" void kernel_launch(void* const* d_in, const int* in_sizes, int n_in,
                              void* d_out, int out_size) {
    (void)out_size;
    const float* inputs = nullptr; const float* w1 = nullptr;
    const float* w2 = nullptr;     const int* mask = nullptr;
    for (int i = 0; i < n_in; i++) {
        int s = in_sizes[i];
        if      (s == Bdim * Ldim * Hdim)    inputs = (const float*)d_in[i];
        else if (s == Hdim * Odim * Hdim)    w1     = (const float*)d_in[i];
        else if (s == (2 * Hdim + 1) * Odim) w2     = (const float*)d_in[i];
        else if (s == Bdim * Ldim)           mask   = (const int*)d_in[i];
    }
    float* out = (float*)d_out;

    cudaFuncSetAttribute(gemm1_kernel, cudaFuncAttributeMaxDynamicSharedMemorySize, SMEM_DYN);
    cudaFuncSetAttribute(gemm2_kernel, cudaFuncAttributeMaxDynamicSharedMemorySize, SMEM_DYN);

    convert_in_kernel<<<(Bdim * Ldim * Hdim) / 1024, 256>>>(inputs);
    transpose_w1_kernel<<<dim3((Odim * Hdim) / 32, Hdim / 32), dim3(32, 8)>>>(w1);
    lin_kernel<<<Bdim * Ldim, 384>>>(inputs, w2);
    gemm1_kernel<<<dim3((Odim * Hdim) / BN, (Bdim * Ldim) / BM), 256, SMEM_DYN>>>();
    gemm2_kernel<<<dim3(Ldim / BN, Ldim / BM, Bdim * Odim), 256, SMEM_DYN>>>(w2, mask, out);
}